// round 8
// baseline (speedup 1.0000x reference)
#include <cuda_runtime.h>
#include <cstdint>

#define NTOK   8192              // B*S
#define T_SLOT 16
#define E_DIM  1024
#define D_DIM  100
#define OUT_W  (E_DIM + D_DIM)   // 1124

__global__ __launch_bounds__(256)
void fuse_triples_wt_kernel(const int*   __restrict__ inputs,   // [NTOK]
                            const int*   __restrict__ triples,  // [NTOK,T,3]
                            const int*   __restrict__ flags,    // [NTOK,T]
                            const float* __restrict__ emb,      // [VOCAB,1024]
                            const float* __restrict__ ent,      // [ENT_VOCAB,100]
                            float*       __restrict__ out)      // [NTOK,1124]
{
    const int gwarp = (blockIdx.x * blockDim.x + threadIdx.x) >> 5;
    const int lane  = threadIdx.x & 31;
    const int token = gwarp;

    // ---- decode triple slots, one slot per lane (lanes 0..15) ----
    int e = -1;
    if (lane < T_SLOT) {
        const int f = flags[token * T_SLOT + lane];
        if (f == 1)      e = triples[(token * T_SLOT + lane) * 3 + 1]; // tail
        else if (f == 2) e = triples[(token * T_SLOT + lane) * 3 + 0]; // head
    }
    const unsigned vmask = __ballot_sync(0xffffffffu, e >= 0);
    const int cnt = __popc(vmask & 0xFFFFu);

    const int vrow = inputs[token];

    // ---- broadcast all 16 indices first: gather loads can issue back-to-back
    int ej[T_SLOT];
    #pragma unroll
    for (int j = 0; j < T_SLOT; ++j)
        ej[j] = __shfl_sync(0xffffffffu, e, j);

    // ---- entity gather + average: lanes 0..24 own one float4 group ----
    float4 acc = make_float4(0.f, 0.f, 0.f, 0.f);
    #pragma unroll
    for (int j = 0; j < T_SLOT; ++j) {
        if (ej[j] >= 0 && lane < 25) {
            const float4 r = reinterpret_cast<const float4*>(
                                 ent + (size_t)ej[j] * D_DIM)[lane];
            acc.x += r.x; acc.y += r.y; acc.z += r.z; acc.w += r.w;
        }
    }
    if (lane < 25) {
        const float inv = 1.0f / (float)(cnt > 0 ? cnt : 1);
        acc.x *= inv; acc.y *= inv; acc.z *= inv; acc.w *= inv;
        // write-through: no L2 residency for output lines
        __stwt(reinterpret_cast<float4*>(out + (size_t)token * OUT_W + E_DIM) + lane,
               acc);
    }

    // ---- token embedding copy: 256 float4 by 32 lanes, 8 iters ----
    const float4* __restrict__ src =
        reinterpret_cast<const float4*>(emb + (size_t)vrow * E_DIM);
    float4* __restrict__ dst =
        reinterpret_cast<float4*>(out + (size_t)token * OUT_W);
    #pragma unroll
    for (int i = 0; i < 8; ++i) {
        const float4 v = src[lane + 32 * i];
        __stwt(dst + lane + 32 * i, v);     // write-through streaming store
    }
}

extern "C" void kernel_launch(void* const* d_in, const int* in_sizes, int n_in,
                              void* d_out, int out_size)
{
    const int*   inputs  = (const int*)  d_in[0];
    const int*   triples = (const int*)  d_in[1];
    const int*   flags   = (const int*)  d_in[2];
    const float* emb     = (const float*)d_in[3];
    const float* ent     = (const float*)d_in[4];
    float*       out     = (float*)      d_out;

    // one warp per token: 8192 warps = 1024 blocks * 8 warps
    fuse_triples_wt_kernel<<<NTOK / 8, 256>>>(inputs, triples, flags, emb, ent, out);
}

// round 10
// speedup vs baseline: 1.5187x; 1.5187x over previous
#include <cuda_runtime.h>
#include <cstdint>

#define NTOK   8192              // B*S
#define T_SLOT 16
#define E_DIM  1024
#define D_DIM  100
#define OUT_W  (E_DIM + D_DIM)   // 1124

// ld.global.nc.v4.f32 with an L2 evict-last cache-policy descriptor
__device__ __forceinline__ float4 ldg_el(const float4* p, uint64_t pol)
{
    float4 v;
    asm volatile("ld.global.nc.L2::cache_hint.v4.f32 {%0,%1,%2,%3}, [%4], %5;"
                 : "=f"(v.x), "=f"(v.y), "=f"(v.z), "=f"(v.w)
                 : "l"(p), "l"(pol));
    return v;
}

__global__ __launch_bounds__(256)
void fuse_triples_el_kernel(const int*   __restrict__ inputs,   // [NTOK]
                            const int*   __restrict__ triples,  // [NTOK,T,3]
                            const int*   __restrict__ flags,    // [NTOK,T]
                            const float* __restrict__ emb,      // [VOCAB,1024]
                            const float* __restrict__ ent,      // [ENT_VOCAB,100]
                            float*       __restrict__ out)      // [NTOK,1124]
{
    const int gwarp = (blockIdx.x * blockDim.x + threadIdx.x) >> 5;
    const int lane  = threadIdx.x & 31;
    const int token = gwarp;

    // L2 evict-last policy for all table reads (keep resident across replays)
    uint64_t pol;
    asm volatile("createpolicy.fractional.L2::evict_last.b64 %0, 1.0;"
                 : "=l"(pol));

    // ---- decode triple slots, one slot per lane (lanes 0..15) ----
    int e = -1;
    if (lane < T_SLOT) {
        const int f = flags[token * T_SLOT + lane];
        if (f == 1)      e = triples[(token * T_SLOT + lane) * 3 + 1]; // tail
        else if (f == 2) e = triples[(token * T_SLOT + lane) * 3 + 0]; // head
    }
    const unsigned vmask = __ballot_sync(0xffffffffu, e >= 0);
    const int cnt = __popc(vmask & 0xFFFFu);

    const int vrow = inputs[token];

    // ---- broadcast indices first so gather loads issue back-to-back ----
    int ej[T_SLOT];
    #pragma unroll
    for (int j = 0; j < T_SLOT; ++j)
        ej[j] = __shfl_sync(0xffffffffu, e, j);

    // ---- entity gather + average: lanes 0..24 own one float4 group ----
    float4 acc = make_float4(0.f, 0.f, 0.f, 0.f);
    #pragma unroll
    for (int j = 0; j < T_SLOT; ++j) {
        if (ej[j] >= 0 && lane < 25) {
            const float4 r = ldg_el(reinterpret_cast<const float4*>(
                                        ent + (size_t)ej[j] * D_DIM) + lane, pol);
            acc.x += r.x; acc.y += r.y; acc.z += r.z; acc.w += r.w;
        }
    }
    if (lane < 25) {
        const float inv = 1.0f / (float)(cnt > 0 ? cnt : 1);
        acc.x *= inv; acc.y *= inv; acc.z *= inv; acc.w *= inv;
        // evict-first store: output must not displace table lines
        __stcs(reinterpret_cast<float4*>(out + (size_t)token * OUT_W + E_DIM) + lane,
               acc);
    }

    // ---- token embedding copy: 256 float4 by 32 lanes, 8 iters ----
    const float4* __restrict__ src =
        reinterpret_cast<const float4*>(emb + (size_t)vrow * E_DIM);
    float4* __restrict__ dst =
        reinterpret_cast<float4*>(out + (size_t)token * OUT_W);
    #pragma unroll
    for (int i = 0; i < 8; ++i) {
        const float4 v = ldg_el(src + lane + 32 * i, pol);
        __stcs(dst + lane + 32 * i, v);
    }
}

extern "C" void kernel_launch(void* const* d_in, const int* in_sizes, int n_in,
                              void* d_out, int out_size)
{
    const int*   inputs  = (const int*)  d_in[0];
    const int*   triples = (const int*)  d_in[1];
    const int*   flags   = (const int*)  d_in[2];
    const float* emb     = (const float*)d_in[3];
    const float* ent     = (const float*)d_in[4];
    float*       out     = (float*)      d_out;

    // one warp per token: 8192 warps = 1024 blocks * 8 warps
    fuse_triples_el_kernel<<<NTOK / 8, 256>>>(inputs, triples, flags, emb, ent, out);
}